// round 1
// baseline (speedup 1.0000x reference)
#include <cuda_runtime.h>

#define G   128
#define F   16
#define NX  100
#define NY  100
#define NZ  8
#define NPTS (NX*NY*NZ)

#define TX  4
#define TY  10
#define TZ  8
#define TPB (TX*TY*TZ)   // 320

// Precomputed per-Gaussian data (written by prep kernel each launch; deterministic)
__device__ float d_mu[G][3];
__device__ float d_ic[G][6];    // inverse covariance (symmetric): [i00,i01,i02,i11,i12,i22]
__device__ float d_opac[G];
__device__ float d_of[G][F];    // opac * feature
__device__ float d_r2[G];       // conservative cull radius^2 = 4*trace(cov)

__global__ void prep_kernel(const float* __restrict__ means,
                            const float* __restrict__ opac,
                            const float* __restrict__ feats,
                            const float* __restrict__ covs) {
    int g = threadIdx.x;
    if (g >= G) return;
    const float* C = covs + g * 9;
    double m00 = C[0], m01 = C[1], m02 = C[2];
    double m10 = C[3], m11 = C[4], m12 = C[5];
    double m20 = C[6], m21 = C[7], m22 = C[8];

    double A00 = m11*m22 - m12*m21;
    double A01 = m02*m21 - m01*m22;
    double A02 = m01*m12 - m02*m11;
    double A10 = m12*m20 - m10*m22;
    double A11 = m00*m22 - m02*m20;
    double A12 = m02*m10 - m00*m12;
    double A20 = m10*m21 - m11*m20;
    double A21 = m01*m20 - m00*m21;
    double A22 = m00*m11 - m01*m10;
    double det = m00*A00 + m01*A10 + m02*A20;
    double id  = 1.0 / det;

    // symmetric inverse (average the numerically-equal off-diagonal cofactors)
    d_ic[g][0] = (float)(A00 * id);
    d_ic[g][1] = (float)(0.5 * (A01 + A10) * id);
    d_ic[g][2] = (float)(0.5 * (A02 + A20) * id);
    d_ic[g][3] = (float)(A11 * id);
    d_ic[g][4] = (float)(0.5 * (A12 + A21) * id);
    d_ic[g][5] = (float)(A22 * id);

    d_mu[g][0] = means[g*3 + 0];
    d_mu[g][1] = means[g*3 + 1];
    d_mu[g][2] = means[g*3 + 2];

    float o = opac[g];
    d_opac[g] = o;
    #pragma unroll
    for (int j = 0; j < F; j++) d_of[g][j] = o * feats[g*F + j];

    // mask needs maha <= 4; maha >= dd/lambda_max >= dd/trace  =>  cull if dd > 4*trace
    float tr = C[0] + C[4] + C[8];
    d_r2[g] = 4.0f * tr * 1.0002f + 1e-3f;
}

__global__ __launch_bounds__(TPB)
void splat_kernel(const float* __restrict__ grid, float* __restrict__ out) {
    __shared__ float s_mu[G][3];
    __shared__ float s_ic[G][6];
    __shared__ float s_opac[G];
    __shared__ float s_of[G][F];
    __shared__ float s_r2[G];
    __shared__ int   s_cnt;

    const int tid = threadIdx.x;
    const int bx  = blockIdx.x;   // 0..24  (x tiles of 4)
    const int by  = blockIdx.y;   // 0..9   (y tiles of 10)

    // Tile AABB (voxel centers; culling bound already has margin)
    const float x0 = (bx*TX + 0.5f) * 0.8f - 40.0f;
    const float x1 = (bx*TX + TX - 0.5f) * 0.8f - 40.0f;
    const float y0 = (by*TY + 0.5f) * 0.8f - 40.0f;
    const float y1 = (by*TY + TY - 0.5f) * 0.8f - 40.0f;
    const float z0 = 0.5f * 0.8f - 1.0f;
    const float z1 = (NZ - 0.5f) * 0.8f - 1.0f;

    if (tid == 0) s_cnt = 0;
    __syncthreads();

    // Stage 1: cull + compact Gaussians touching this tile into shared memory
    if (tid < G) {
        float mx = d_mu[tid][0], my = d_mu[tid][1], mz = d_mu[tid][2];
        float cx = fminf(fmaxf(mx, x0), x1) - mx;
        float cy = fminf(fmaxf(my, y0), y1) - my;
        float cz = fminf(fmaxf(mz, z0), z1) - mz;
        float dd = cx*cx + cy*cy + cz*cz;
        float r2 = d_r2[tid];
        if (dd <= r2) {
            int k = atomicAdd(&s_cnt, 1);
            s_mu[k][0] = mx; s_mu[k][1] = my; s_mu[k][2] = mz;
            #pragma unroll
            for (int j = 0; j < 6; j++) s_ic[k][j] = d_ic[tid][j];
            s_opac[k] = d_opac[tid];
            #pragma unroll
            for (int j = 0; j < F; j++) s_of[k][j] = d_of[tid][j];
            s_r2[k] = r2;
        }
    }
    __syncthreads();
    const int ng = s_cnt;

    // Stage 2: per-point accumulation
    const int tz = tid & (TZ - 1);
    const int ty = (tid / TZ) % TY;
    const int tx = tid / (TZ * TY);
    const int x = bx*TX + tx;
    const int y = by*TY + ty;
    const int z = tz;
    const int n = (x * NY + y) * NZ + z;

    const float px = grid[n*3 + 0];
    const float py = grid[n*3 + 1];
    const float pz = grid[n*3 + 2];

    float sum_d = 0.0f, cnt = 0.0f;
    float sf[F];
    #pragma unroll
    for (int j = 0; j < F; j++) sf[j] = 0.0f;

    for (int k = 0; k < ng; k++) {
        float dx = px - s_mu[k][0];
        float dy = py - s_mu[k][1];
        float dz = pz - s_mu[k][2];
        float dd = dx*dx + dy*dy + dz*dz;
        if (dd > s_r2[k]) continue;

        float maha = s_ic[k][0]*dx*dx + s_ic[k][3]*dy*dy + s_ic[k][5]*dz*dz
                   + 2.0f * (s_ic[k][1]*dx*dy + s_ic[k][2]*dx*dz + s_ic[k][4]*dy*dz);
        if (maha <= 4.0f) {
            float w = __expf(-0.5f * maha);
            cnt += 1.0f;
            sum_d += s_opac[k] * w;
            #pragma unroll
            for (int j = 0; j < F; j++) sf[j] += s_of[k][j] * w;
        }
    }

    const float invc = (cnt > 0.0f) ? (1.0f / cnt) : 0.0f;
    out[n] = sum_d * invc;

    float4* fo = reinterpret_cast<float4*>(out + NPTS + (size_t)n * F);
    #pragma unroll
    for (int j = 0; j < F/4; j++) {
        float4 v;
        v.x = sf[j*4 + 0] * invc;
        v.y = sf[j*4 + 1] * invc;
        v.z = sf[j*4 + 2] * invc;
        v.w = sf[j*4 + 3] * invc;
        fo[j] = v;
    }
}

extern "C" void kernel_launch(void* const* d_in, const int* in_sizes, int n_in,
                              void* d_out, int out_size) {
    const float* grid   = (const float*)d_in[0];  // (80000, 3)
    const float* means  = (const float*)d_in[1];  // (1, 128, 3)
    const float* opac   = (const float*)d_in[2];  // (1, 128, 1)
    const float* feats  = (const float*)d_in[3];  // (1, 128, 16)
    const float* covs   = (const float*)d_in[4];  // (1, 128, 3, 3)
    float* out = (float*)d_out;                   // [dens 80000 | feats 80000*16]

    prep_kernel<<<1, G>>>(means, opac, feats, covs);
    dim3 gridDim(NX / TX, NY / TY);   // (25, 10)
    splat_kernel<<<gridDim, TPB>>>(grid, out);
}